// round 2
// baseline (speedup 1.0000x reference)
#include <cuda_runtime.h>
#include <math.h>

#define BB 4
#define SS 2048
#define HH 1024
#define NH 16
#define HD 64
#define MM (BB*SS)          // 8192 rows

// ---------------- scratch (device globals; no allocation allowed) ----------
__device__ float g_y[BB*SS*HH];        // LN output            32 MB
__device__ float g_q[BB*NH*SS*HD];     // Q  [b,h,s,d]         32 MB
__device__ float g_k[BB*NH*SS*HD];     // K  [b,h,s,d]         32 MB
__device__ float g_v[BB*NH*SS*HD];     // V  [b,h,s,d]         32 MB
__device__ float g_ctx[BB*SS*HH];      // attention context    32 MB

// ---------------- packed fp32x2 helpers (Blackwell FFMA2 path) -------------
typedef unsigned long long u64;

__device__ __forceinline__ u64 pk2(float x) {            // (x, x)
    u64 r; asm("mov.b64 %0, {%1, %1};" : "=l"(r) : "f"(x)); return r;
}
__device__ __forceinline__ void fma2(u64& c, u64 a, u64 b) {
    asm("fma.rn.f32x2 %0, %1, %2, %0;" : "+l"(c) : "l"(a), "l"(b));
}
__device__ __forceinline__ void mul2(u64& c, u64 a) {
    asm("mul.rn.f32x2 %0, %0, %1;" : "+l"(c) : "l"(a));
}
__device__ __forceinline__ float2 up2(u64 v) {
    float2 f; asm("mov.b64 {%0, %1}, %2;" : "=f"(f.x), "=f"(f.y) : "l"(v)); return f;
}
__device__ __forceinline__ u64 ld2(const float* p) {     // 8B-aligned pair load
    return *(const u64*)p;
}

// ======================= 1) LayerNorm ======================================
__global__ void __launch_bounds__(256) ln_kernel(
    const float* __restrict__ x,
    const float* __restrict__ gamma,
    const float* __restrict__ beta)
{
    int row = blockIdx.x;
    int tid = threadIdx.x;
    const float4 xv = *(const float4*)&x[row*HH + tid*4];

    float s  = xv.x + xv.y + xv.z + xv.w;
    float s2 = xv.x*xv.x + xv.y*xv.y + xv.z*xv.z + xv.w*xv.w;
    #pragma unroll
    for (int o = 16; o > 0; o >>= 1) {
        s  += __shfl_down_sync(0xffffffffu, s,  o);
        s2 += __shfl_down_sync(0xffffffffu, s2, o);
    }
    __shared__ float ss[8], ss2[8];
    if ((tid & 31) == 0) { ss[tid >> 5] = s; ss2[tid >> 5] = s2; }
    __syncthreads();
    float ts = 0.f, ts2 = 0.f;
    #pragma unroll
    for (int w = 0; w < 8; w++) { ts += ss[w]; ts2 += ss2[w]; }

    float mu   = ts * (1.0f / HH);
    float var  = ts2 * (1.0f / HH) - mu * mu;
    float rstd = rsqrtf(var + 1e-5f);

    const float4 gv = *(const float4*)&gamma[tid*4];
    const float4 bv = *(const float4*)&beta[tid*4];
    float4 yv;
    yv.x = (xv.x - mu) * rstd * gv.x + bv.x;
    yv.y = (xv.y - mu) * rstd * gv.y + bv.y;
    yv.z = (xv.z - mu) * rstd * gv.z + bv.z;
    yv.w = (xv.w - mu) * rstd * gv.w + bv.w;
    *(float4*)&g_y[row*HH + tid*4] = yv;
}

// ======================= 2) QKV GEMM (128x128x8, FFMA2) ====================
// C[m,n] = sum_k y[m,k] * qkv_w[n,k] + qkv_b[n];  M=8192, N=3072, K=1024
// smem transposed [k][row], stride 132 (conflict-free transpose stores).
// 8x8 microtile; n-pairs packed as f32x2 (loaded directly as double2).
__global__ void __launch_bounds__(256) gemm_qkv_kernel(
    const float* __restrict__ W,
    const float* __restrict__ bias)
{
    __shared__ float As[8*132];
    __shared__ float Bs[8*132];
    int tid = threadIdx.x;
    int tx = tid & 15, ty = tid >> 4;
    int n0 = blockIdx.x * 128;
    int m0 = blockIdx.y * 128;

    int lr = tid >> 1;            // 0..127
    int lk = (tid & 1) * 4;       // 0 or 4

    const float* Ap = g_y + (size_t)(m0 + lr) * HH + lk;
    const float* Bp = W   + (size_t)(n0 + lr) * HH + lk;

    u64 acc2[8][4] = {};

    for (int k0 = 0; k0 < HH; k0 += 8) {
        float4 a  = *(const float4*)(Ap + k0);
        float4 bv = *(const float4*)(Bp + k0);
        __syncthreads();
        As[(lk+0)*132+lr] = a.x;  As[(lk+1)*132+lr] = a.y;
        As[(lk+2)*132+lr] = a.z;  As[(lk+3)*132+lr] = a.w;
        Bs[(lk+0)*132+lr] = bv.x; Bs[(lk+1)*132+lr] = bv.y;
        Bs[(lk+2)*132+lr] = bv.z; Bs[(lk+3)*132+lr] = bv.w;
        __syncthreads();
        #pragma unroll
        for (int kk = 0; kk < 8; kk++) {
            float4 a0 = *(float4*)&As[kk*132 + ty*8];
            float4 a1 = *(float4*)&As[kk*132 + ty*8 + 4];
            double2 b0 = *(double2*)&Bs[kk*132 + tx*8];
            double2 b1 = *(double2*)&Bs[kk*132 + tx*8 + 4];
            u64 pb[4] = { __double_as_longlong(b0.x), __double_as_longlong(b0.y),
                          __double_as_longlong(b1.x), __double_as_longlong(b1.y) };
            float af[8] = {a0.x,a0.y,a0.z,a0.w,a1.x,a1.y,a1.z,a1.w};
            #pragma unroll
            for (int i = 0; i < 8; i++) {
                u64 pa = pk2(af[i]);
                #pragma unroll
                for (int j = 0; j < 4; j++) fma2(acc2[i][j], pa, pb[j]);
            }
        }
    }

    // epilogue: scatter into g_q/g_k/g_v [b,h,s,d]
    #pragma unroll
    for (int i = 0; i < 8; i++) {
        int m = m0 + ty*8 + i;
        int b = m >> 11;             // /2048
        int s = m & 2047;
        #pragma unroll
        for (int cc = 0; cc < 2; cc++) {
            int nb = n0 + tx*8 + cc*4;
            int grp  = nb >> 10;
            int head = (nb & 1023) >> 6;
            int d    = nb & 63;
            float* dst = (grp == 0) ? g_q : (grp == 1) ? g_k : g_v;
            float2 p0 = up2(acc2[i][cc*2 + 0]);
            float2 p1 = up2(acc2[i][cc*2 + 1]);
            const float4 bia = *(const float4*)&bias[nb];
            float4 out;
            out.x = p0.x + bia.x; out.y = p0.y + bia.y;
            out.z = p1.x + bia.z; out.w = p1.y + bia.w;
            *(float4*)&dst[((size_t)(b*NH + head)*SS + s)*HD + d] = out;
        }
    }
}

// ======================= 3) Flash attention (FFMA2 over reduction dim) =====
// grid (32 q-tiles, 64 bh); 256 threads (16x16); 64x64 tiles, online softmax.
// QK packs d-pairs, PV packs k-pairs (contiguous pairs -> no repacking).
// dyn smem = 67072 B.
__global__ void __launch_bounds__(256) attn_kernel(const int* __restrict__ mask)
{
    extern __shared__ float sm[];
    float* Qs  = sm;                     // [64][64]
    float* Ks  = sm + 4096;              // [64][66]  (row = key, col = d)
    float* VsT = sm + 4096 + 4224;       // [64][66]  (row = d, col = key)
    float* Ps  = sm + 4096 + 2*4224;     // [64][66]  (row = q,  col = key)

    int tid = threadIdx.x;
    int tx = tid & 15, ty = tid >> 4;
    int bh = blockIdx.y;
    int q0 = blockIdx.x * 64;
    int b  = bh >> 4, h = bh & 15;

    const float* Qg = g_q + (size_t)bh * SS * HD;
    const float* Kg = g_k + (size_t)bh * SS * HD;
    const float* Vg = g_v + (size_t)bh * SS * HD;

    // load Q tile
    #pragma unroll
    for (int r = 0; r < 4; r++) {
        int idx = tid + r*256;
        int q = idx >> 4, dg = idx & 15;
        float4 v = *(const float4*)&Qg[(size_t)(q0 + q)*HD + dg*4];
        *(float4*)&Qs[q*64 + dg*4] = v;
    }

    u64 o2[4][4] = {};
    float mrun[4] = {-1e30f, -1e30f, -1e30f, -1e30f};
    float lrun[4] = {};

    for (int k0 = 0; k0 < SS; k0 += 64) {
        __syncthreads();  // protect Ks/VsT/Ps from previous iteration readers
        #pragma unroll
        for (int r = 0; r < 4; r++) {
            int idx = tid + r*256;
            int kk = idx >> 4, dg = idx & 15;
            float4 kv = *(const float4*)&Kg[(size_t)(k0 + kk)*HD + dg*4];
            Ks[kk*66 + dg*4 + 0] = kv.x;
            Ks[kk*66 + dg*4 + 1] = kv.y;
            Ks[kk*66 + dg*4 + 2] = kv.z;
            Ks[kk*66 + dg*4 + 3] = kv.w;
            float4 vv = *(const float4*)&Vg[(size_t)(k0 + kk)*HD + dg*4];
            VsT[(dg*4 + 0)*66 + kk] = vv.x;
            VsT[(dg*4 + 1)*66 + kk] = vv.y;
            VsT[(dg*4 + 2)*66 + kk] = vv.z;
            VsT[(dg*4 + 3)*66 + kk] = vv.w;
        }
        __syncthreads();

        // S = Q K^T  (packed over d)
        u64 s2[4][4] = {};
        #pragma unroll 4
        for (int d = 0; d < 64; d += 2) {
            u64 qv[4], kv[4];
            #pragma unroll
            for (int i = 0; i < 4; i++) qv[i] = ld2(&Qs[(ty*4 + i)*64 + d]);
            #pragma unroll
            for (int j = 0; j < 4; j++) kv[j] = ld2(&Ks[(tx*4 + j)*66 + d]);
            #pragma unroll
            for (int i = 0; i < 4; i++)
                #pragma unroll
                for (int j = 0; j < 4; j++)
                    fma2(s2[i][j], qv[i], kv[j]);
        }

        float biasj[4];
        #pragma unroll
        for (int j = 0; j < 4; j++)
            biasj[j] = -1e8f * (float)mask[b*SS + k0 + tx*4 + j];

        // online softmax per query row
        #pragma unroll
        for (int i = 0; i < 4; i++) {
            float srow[4];
            float tm = -1e30f;
            #pragma unroll
            for (int j = 0; j < 4; j++) {
                float2 f = up2(s2[i][j]);
                srow[j] = (f.x + f.y) * 0.125f + biasj[j];
                tm = fmaxf(tm, srow[j]);
            }
            #pragma unroll
            for (int off = 8; off > 0; off >>= 1)
                tm = fmaxf(tm, __shfl_xor_sync(0xffffffffu, tm, off));
            float mnew = fmaxf(mrun[i], tm);
            float fac  = __expf(mrun[i] - mnew);
            mrun[i] = mnew;
            float psum = 0.f;
            #pragma unroll
            for (int j = 0; j < 4; j++) {
                float p = __expf(srow[j] - mnew);
                Ps[(ty*4 + i)*66 + tx*4 + j] = p;
                psum += p;
            }
            #pragma unroll
            for (int off = 8; off > 0; off >>= 1)
                psum += __shfl_xor_sync(0xffffffffu, psum, off);
            lrun[i] = lrun[i] * fac + psum;
            u64 fac2 = pk2(fac);
            #pragma unroll
            for (int j = 0; j < 4; j++) mul2(o2[i][j], fac2);
        }
        __syncthreads();

        // O += P V  (packed over k)
        #pragma unroll 4
        for (int k = 0; k < 64; k += 2) {
            u64 pv[4], vv[4];
            #pragma unroll
            for (int i = 0; i < 4; i++) pv[i] = ld2(&Ps[(ty*4 + i)*66 + k]);
            #pragma unroll
            for (int j = 0; j < 4; j++) vv[j] = ld2(&VsT[(tx*4 + j)*66 + k]);
            #pragma unroll
            for (int i = 0; i < 4; i++)
                #pragma unroll
                for (int j = 0; j < 4; j++)
                    fma2(o2[i][j], pv[i], vv[j]);
        }
    }

    // write ctx in [b, s, h*64+d] layout (horizontal add of the k-pairs)
    #pragma unroll
    for (int i = 0; i < 4; i++) {
        float inv = 1.0f / lrun[i];
        float c[4];
        #pragma unroll
        for (int j = 0; j < 4; j++) {
            float2 f = up2(o2[i][j]);
            c[j] = (f.x + f.y) * inv;
        }
        float4 out = {c[0], c[1], c[2], c[3]};
        *(float4*)&g_ctx[((size_t)b*SS + q0 + ty*4 + i)*HH + h*HD + tx*4] = out;
    }
}

// ======================= 4) Output GEMM + bias + residual ==================
// out[m,n] = sum_k ctx[m,k] * out_w[n,k] + out_b[n] + x[m,n]
__global__ void __launch_bounds__(256) gemm_out_kernel(
    const float* __restrict__ W,
    const float* __restrict__ bias,
    const float* __restrict__ x,
    float* __restrict__ out)
{
    __shared__ float As[8*132];
    __shared__ float Bs[8*132];
    int tid = threadIdx.x;
    int tx = tid & 15, ty = tid >> 4;
    int n0 = blockIdx.x * 128;
    int m0 = blockIdx.y * 128;

    int lr = tid >> 1;
    int lk = (tid & 1) * 4;

    const float* Ap = g_ctx + (size_t)(m0 + lr) * HH + lk;
    const float* Bp = W     + (size_t)(n0 + lr) * HH + lk;

    u64 acc2[8][4] = {};

    for (int k0 = 0; k0 < HH; k0 += 8) {
        float4 a  = *(const float4*)(Ap + k0);
        float4 bv = *(const float4*)(Bp + k0);
        __syncthreads();
        As[(lk+0)*132+lr] = a.x;  As[(lk+1)*132+lr] = a.y;
        As[(lk+2)*132+lr] = a.z;  As[(lk+3)*132+lr] = a.w;
        Bs[(lk+0)*132+lr] = bv.x; Bs[(lk+1)*132+lr] = bv.y;
        Bs[(lk+2)*132+lr] = bv.z; Bs[(lk+3)*132+lr] = bv.w;
        __syncthreads();
        #pragma unroll
        for (int kk = 0; kk < 8; kk++) {
            float4 a0 = *(float4*)&As[kk*132 + ty*8];
            float4 a1 = *(float4*)&As[kk*132 + ty*8 + 4];
            double2 b0 = *(double2*)&Bs[kk*132 + tx*8];
            double2 b1 = *(double2*)&Bs[kk*132 + tx*8 + 4];
            u64 pb[4] = { __double_as_longlong(b0.x), __double_as_longlong(b0.y),
                          __double_as_longlong(b1.x), __double_as_longlong(b1.y) };
            float af[8] = {a0.x,a0.y,a0.z,a0.w,a1.x,a1.y,a1.z,a1.w};
            #pragma unroll
            for (int i = 0; i < 8; i++) {
                u64 pa = pk2(af[i]);
                #pragma unroll
                for (int j = 0; j < 4; j++) fma2(acc2[i][j], pa, pb[j]);
            }
        }
    }

    #pragma unroll
    for (int i = 0; i < 8; i++) {
        int m = m0 + ty*8 + i;
        #pragma unroll
        for (int cc = 0; cc < 2; cc++) {
            int nb = n0 + tx*8 + cc*4;
            float2 p0 = up2(acc2[i][cc*2 + 0]);
            float2 p1 = up2(acc2[i][cc*2 + 1]);
            const float4 bia = *(const float4*)&bias[nb];
            const float4 xr  = *(const float4*)&x[(size_t)m*HH + nb];
            float4 outv;
            outv.x = p0.x + bia.x + xr.x;
            outv.y = p0.y + bia.y + xr.y;
            outv.z = p1.x + bia.z + xr.z;
            outv.w = p1.y + bia.w + xr.w;
            *(float4*)&out[(size_t)m*HH + nb] = outv;
        }
    }
}

// ======================= launch ============================================
extern "C" void kernel_launch(void* const* d_in, const int* in_sizes, int n_in,
                              void* d_out, int out_size)
{
    const float* x      = (const float*)d_in[0];
    const int*   mask   = (const int*)  d_in[1];
    const float* qkv_w  = (const float*)d_in[2];
    const float* qkv_b  = (const float*)d_in[3];
    const float* out_w  = (const float*)d_in[4];
    const float* out_b  = (const float*)d_in[5];
    const float* gamma  = (const float*)d_in[6];
    const float* beta   = (const float*)d_in[7];
    float* out = (float*)d_out;

    // attention kernel needs 67072 B dynamic smem (idempotent, capture-safe)
    cudaFuncSetAttribute(attn_kernel,
                         cudaFuncAttributeMaxDynamicSharedMemorySize, 67072);

    // 1) LayerNorm
    ln_kernel<<<MM, 256>>>(x, gamma, beta);

    // 2) QKV projection: N=3072, M=8192, 128x128 tiles
    gemm_qkv_kernel<<<dim3(3*HH/128, MM/128), 256>>>(qkv_w, qkv_b);

    // 3) attention
    attn_kernel<<<dim3(SS/64, BB*NH), 256, 67072>>>(mask);

    // 4) output projection + bias + residual
    gemm_out_kernel<<<dim3(HH/128, MM/128), 256>>>(out_w, out_b, x, out);
}

// round 3
// speedup vs baseline: 4.3971x; 4.3971x over previous
#include <cuda_runtime.h>
#include <math.h>

#define BB 4
#define SS 2048
#define HH 1024
#define NH 16
#define HD 64
#define MM (BB*SS)          // 8192 rows

// ---------------- scratch (device globals; no allocation allowed) ----------
__device__ float g_y[BB*SS*HH];        // LN output            32 MB
__device__ float g_q[BB*NH*SS*HD];     // Q  [b,h,s,d]         32 MB
__device__ float g_k[BB*NH*SS*HD];     // K  [b,h,s,d]         32 MB
__device__ float g_v[BB*NH*SS*HD];     // V  [b,h,s,d]         32 MB
__device__ float g_ctx[BB*SS*HH];      // attention context    32 MB

// ---------------- tf32 mma helpers -----------------------------------------
__device__ __forceinline__ unsigned f2tf(float x) {
    unsigned r; asm("cvt.rna.tf32.f32 %0, %1;" : "=r"(r) : "f"(x)); return r;
}
// D(16x8,f32) += A(16x8,tf32,row) * B(8x8,tf32,col)
__device__ __forceinline__ void mma_tf32(float* d, const unsigned* a, const unsigned* b) {
    asm("mma.sync.aligned.m16n8k8.row.col.f32.tf32.tf32.f32 "
        "{%0,%1,%2,%3},{%4,%5,%6,%7},{%8,%9},{%0,%1,%2,%3};"
        : "+f"(d[0]), "+f"(d[1]), "+f"(d[2]), "+f"(d[3])
        : "r"(a[0]), "r"(a[1]), "r"(a[2]), "r"(a[3]), "r"(b[0]), "r"(b[1]));
}
__device__ __forceinline__ void ldsm_x4(unsigned* r, unsigned addr) {
    asm volatile("ldmatrix.sync.aligned.m8n8.x4.shared.b16 {%0,%1,%2,%3},[%4];"
        : "=r"(r[0]), "=r"(r[1]), "=r"(r[2]), "=r"(r[3]) : "r"(addr));
}
__device__ __forceinline__ void ldsm_x2(unsigned* r, unsigned addr) {
    asm volatile("ldmatrix.sync.aligned.m8n8.x2.shared.b16 {%0,%1},[%2];"
        : "=r"(r[0]), "=r"(r[1]) : "r"(addr));
}

// ======================= 1) LayerNorm ======================================
__global__ void __launch_bounds__(256) ln_kernel(
    const float* __restrict__ x,
    const float* __restrict__ gamma,
    const float* __restrict__ beta)
{
    int row = blockIdx.x;
    int tid = threadIdx.x;
    const float4 xv = *(const float4*)&x[row*HH + tid*4];

    float s  = xv.x + xv.y + xv.z + xv.w;
    float s2 = xv.x*xv.x + xv.y*xv.y + xv.z*xv.z + xv.w*xv.w;
    #pragma unroll
    for (int o = 16; o > 0; o >>= 1) {
        s  += __shfl_down_sync(0xffffffffu, s,  o);
        s2 += __shfl_down_sync(0xffffffffu, s2, o);
    }
    __shared__ float ss[8], ss2[8];
    if ((tid & 31) == 0) { ss[tid >> 5] = s; ss2[tid >> 5] = s2; }
    __syncthreads();
    float ts = 0.f, ts2 = 0.f;
    #pragma unroll
    for (int w = 0; w < 8; w++) { ts += ss[w]; ts2 += ss2[w]; }

    float mu   = ts * (1.0f / HH);
    float var  = ts2 * (1.0f / HH) - mu * mu;
    float rstd = rsqrtf(var + 1e-5f);

    const float4 gv = *(const float4*)&gamma[tid*4];
    const float4 bv = *(const float4*)&beta[tid*4];
    float4 yv;
    yv.x = (xv.x - mu) * rstd * gv.x + bv.x;
    yv.y = (xv.y - mu) * rstd * gv.y + bv.y;
    yv.z = (xv.z - mu) * rstd * gv.z + bv.z;
    yv.w = (xv.w - mu) * rstd * gv.w + bv.w;
    *(float4*)&g_y[row*HH + tid*4] = yv;
}

// ======================= TF32 GEMM core (128x128, k-step 32) ===============
// C[m,n] = sum_k A[m,k] * W[n,k]   (both k-contiguous -> mma row.col)
// 8 warps as 2(m) x 4(n); warp tile 64x32 = 4 m-tiles x 4 n-tiles of m16n8k8.
#define GST 36   // smem row stride (words); 36 mod 32 = 4 -> conflict-free LDSM

// ---- QKV GEMM: epilogue scatters to g_q/g_k/g_v in [b,h,s,d] --------------
__global__ void __launch_bounds__(256) gemm_qkv_kernel(
    const float* __restrict__ W,
    const float* __restrict__ bias)
{
    __shared__ float As[128*GST];
    __shared__ float Bs[128*GST];
    const int tid  = threadIdx.x;
    const int lane = tid & 31;
    const int w    = tid >> 5;
    const int warp_m = (w >> 2) * 64;
    const int warp_n = (w & 3) * 32;
    const int n0 = blockIdx.x * 128;
    const int m0 = blockIdx.y * 128;

    // staging: thread handles rows sr, sr+64, cols sc..sc+7
    const int sr = tid >> 2;
    const int sc = (tid & 3) * 8;
    const float* Ap = g_y + (size_t)(m0 + sr) * HH + sc;
    const float* Bp = W   + (size_t)(n0 + sr) * HH + sc;

    unsigned AsB = (unsigned)__cvta_generic_to_shared(As);
    unsigned BsB = (unsigned)__cvta_generic_to_shared(Bs);

    // fragment lane addressing
    const int arow  = (lane & 7) + ((lane >> 3) & 1) * 8;
    const int ahalf = (lane >> 4) * 4;
    const unsigned aBase = AsB + (unsigned)(((warp_m + arow) * GST + ahalf) * 4);
    const int brow  = lane & 7;
    const int bhalf = ((lane >> 3) & 1) * 4;
    const unsigned bBase = BsB + (unsigned)(((warp_n + brow) * GST + bhalf) * 4);

    float acc[4][4][4] = {};
    float4 ra[2][2], rb[2][2];
    #pragma unroll
    for (int hf = 0; hf < 2; hf++)
        #pragma unroll
        for (int q = 0; q < 2; q++) {
            ra[hf][q] = *(const float4*)(Ap + (size_t)hf*64*HH + q*4);
            rb[hf][q] = *(const float4*)(Bp + (size_t)hf*64*HH + q*4);
        }

    for (int k0 = 0; k0 < HH; k0 += 32) {
        __syncthreads();
        #pragma unroll
        for (int hf = 0; hf < 2; hf++)
            #pragma unroll
            for (int q = 0; q < 2; q++) {
                float4 va = ra[hf][q];
                uint4 ua = {f2tf(va.x), f2tf(va.y), f2tf(va.z), f2tf(va.w)};
                *(uint4*)&As[(sr + hf*64)*GST + sc + q*4] = ua;
                float4 vb = rb[hf][q];
                uint4 ub = {f2tf(vb.x), f2tf(vb.y), f2tf(vb.z), f2tf(vb.w)};
                *(uint4*)&Bs[(sr + hf*64)*GST + sc + q*4] = ub;
            }
        __syncthreads();
        if (k0 + 32 < HH) {
            #pragma unroll
            for (int hf = 0; hf < 2; hf++)
                #pragma unroll
                for (int q = 0; q < 2; q++) {
                    ra[hf][q] = *(const float4*)(Ap + k0 + 32 + (size_t)hf*64*HH + q*4);
                    rb[hf][q] = *(const float4*)(Bp + k0 + 32 + (size_t)hf*64*HH + q*4);
                }
        }
        #pragma unroll
        for (int kc = 0; kc < 4; kc++) {
            unsigned af[4][4], bf[4][2];
            #pragma unroll
            for (int mt = 0; mt < 4; mt++)
                ldsm_x4(af[mt], aBase + (unsigned)((mt*16*GST + kc*8) * 4));
            #pragma unroll
            for (int nt = 0; nt < 4; nt++)
                ldsm_x2(bf[nt], bBase + (unsigned)((nt*8*GST + kc*8) * 4));
            #pragma unroll
            for (int mt = 0; mt < 4; mt++)
                #pragma unroll
                for (int nt = 0; nt < 4; nt++)
                    mma_tf32(acc[mt][nt], af[mt], bf[nt]);
        }
    }

    // epilogue: scatter to q/k/v [b,h,s,d]
    const int g = lane >> 2, t2 = (lane & 3) * 2;
    #pragma unroll
    for (int nt = 0; nt < 4; nt++) {
        int gn = n0 + warp_n + nt*8 + t2;
        int grp = gn >> 10, head = (gn >> 6) & 15, d = gn & 63;
        float* dst = (grp == 0) ? g_q : (grp == 1) ? g_k : g_v;
        float2 bi = *(const float2*)&bias[gn];
        #pragma unroll
        for (int mt = 0; mt < 4; mt++) {
            int m = m0 + warp_m + mt*16 + g;
            int b = m >> 11, s = m & 2047;
            float* p = &dst[((size_t)(b*NH + head)*SS + s)*HD + d];
            float2 v0 = {acc[mt][nt][0] + bi.x, acc[mt][nt][1] + bi.y};
            *(float2*)p = v0;
            float2 v1 = {acc[mt][nt][2] + bi.x, acc[mt][nt][3] + bi.y};
            *(float2*)(p + 8*HD) = v1;
        }
    }
}

// ---- Output GEMM: + bias + residual ---------------------------------------
__global__ void __launch_bounds__(256) gemm_out_kernel(
    const float* __restrict__ W,
    const float* __restrict__ bias,
    const float* __restrict__ x,
    float* __restrict__ out)
{
    __shared__ float As[128*GST];
    __shared__ float Bs[128*GST];
    const int tid  = threadIdx.x;
    const int lane = tid & 31;
    const int w    = tid >> 5;
    const int warp_m = (w >> 2) * 64;
    const int warp_n = (w & 3) * 32;
    const int n0 = blockIdx.x * 128;
    const int m0 = blockIdx.y * 128;

    const int sr = tid >> 2;
    const int sc = (tid & 3) * 8;
    const float* Ap = g_ctx + (size_t)(m0 + sr) * HH + sc;
    const float* Bp = W     + (size_t)(n0 + sr) * HH + sc;

    unsigned AsB = (unsigned)__cvta_generic_to_shared(As);
    unsigned BsB = (unsigned)__cvta_generic_to_shared(Bs);

    const int arow  = (lane & 7) + ((lane >> 3) & 1) * 8;
    const int ahalf = (lane >> 4) * 4;
    const unsigned aBase = AsB + (unsigned)(((warp_m + arow) * GST + ahalf) * 4);
    const int brow  = lane & 7;
    const int bhalf = ((lane >> 3) & 1) * 4;
    const unsigned bBase = BsB + (unsigned)(((warp_n + brow) * GST + bhalf) * 4);

    float acc[4][4][4] = {};
    float4 ra[2][2], rb[2][2];
    #pragma unroll
    for (int hf = 0; hf < 2; hf++)
        #pragma unroll
        for (int q = 0; q < 2; q++) {
            ra[hf][q] = *(const float4*)(Ap + (size_t)hf*64*HH + q*4);
            rb[hf][q] = *(const float4*)(Bp + (size_t)hf*64*HH + q*4);
        }

    for (int k0 = 0; k0 < HH; k0 += 32) {
        __syncthreads();
        #pragma unroll
        for (int hf = 0; hf < 2; hf++)
            #pragma unroll
            for (int q = 0; q < 2; q++) {
                float4 va = ra[hf][q];
                uint4 ua = {f2tf(va.x), f2tf(va.y), f2tf(va.z), f2tf(va.w)};
                *(uint4*)&As[(sr + hf*64)*GST + sc + q*4] = ua;
                float4 vb = rb[hf][q];
                uint4 ub = {f2tf(vb.x), f2tf(vb.y), f2tf(vb.z), f2tf(vb.w)};
                *(uint4*)&Bs[(sr + hf*64)*GST + sc + q*4] = ub;
            }
        __syncthreads();
        if (k0 + 32 < HH) {
            #pragma unroll
            for (int hf = 0; hf < 2; hf++)
                #pragma unroll
                for (int q = 0; q < 2; q++) {
                    ra[hf][q] = *(const float4*)(Ap + k0 + 32 + (size_t)hf*64*HH + q*4);
                    rb[hf][q] = *(const float4*)(Bp + k0 + 32 + (size_t)hf*64*HH + q*4);
                }
        }
        #pragma unroll
        for (int kc = 0; kc < 4; kc++) {
            unsigned af[4][4], bf[4][2];
            #pragma unroll
            for (int mt = 0; mt < 4; mt++)
                ldsm_x4(af[mt], aBase + (unsigned)((mt*16*GST + kc*8) * 4));
            #pragma unroll
            for (int nt = 0; nt < 4; nt++)
                ldsm_x2(bf[nt], bBase + (unsigned)((nt*8*GST + kc*8) * 4));
            #pragma unroll
            for (int mt = 0; mt < 4; mt++)
                #pragma unroll
                for (int nt = 0; nt < 4; nt++)
                    mma_tf32(acc[mt][nt], af[mt], bf[nt]);
        }
    }

    const int g = lane >> 2, t2 = (lane & 3) * 2;
    #pragma unroll
    for (int nt = 0; nt < 4; nt++) {
        int gn = n0 + warp_n + nt*8 + t2;
        float2 bi = *(const float2*)&bias[gn];
        #pragma unroll
        for (int mt = 0; mt < 4; mt++) {
            int m = m0 + warp_m + mt*16 + g;
            const float2 x0 = *(const float2*)&x[(size_t)m*HH + gn];
            const float2 x1 = *(const float2*)&x[(size_t)(m+8)*HH + gn];
            float2 v0 = {acc[mt][nt][0] + bi.x + x0.x, acc[mt][nt][1] + bi.y + x0.y};
            float2 v1 = {acc[mt][nt][2] + bi.x + x1.x, acc[mt][nt][3] + bi.y + x1.y};
            *(float2*)&out[(size_t)m*HH + gn]     = v0;
            *(float2*)&out[(size_t)(m+8)*HH + gn] = v1;
        }
    }
}

// ======================= 3) Flash attention (tf32 mma) =====================
// 256 threads (8 warps); q-tile 128 (16 rows/warp), k-tile 64.
// Each warp: S = Q K^T (8 d-chunks x 8 n-tiles), warp-local online softmax,
// then O += P V with P converted C-layout -> A-fragment via shuffles.
#define AST 68   // smem row stride (words); 68 mod 32 = 4 -> conflict-free LDSM
__global__ void __launch_bounds__(256) attn_kernel(const int* __restrict__ mask)
{
    extern __shared__ float sm[];
    float* Qs  = sm;                 // [128][AST]
    float* Ks  = sm + 128*AST;       // [64][AST]   row=key, col=d
    float* VsT = sm + 192*AST;       // [64][AST]   row=d,   col=key
    float* ms  = sm + 256*AST;       // [64] mask bias

    const int tid  = threadIdx.x;
    const int lane = tid & 31;
    const int w    = tid >> 5;
    const int bh = blockIdx.y;
    const int q0 = blockIdx.x * 128;
    const int b  = bh >> 4, h = bh & 15;

    const float* Qg = g_q + (size_t)bh * SS * HD;
    const float* Kg = g_k + (size_t)bh * SS * HD;
    const float* Vg = g_v + (size_t)bh * SS * HD;
    const int*   mg = mask + b * SS;

    unsigned smB = (unsigned)__cvta_generic_to_shared(sm);
    const unsigned QsB = smB;
    const unsigned KsB = smB + 128*AST*4;
    const unsigned VsB = smB + 192*AST*4;

    // stage Q (cvt to tf32): thread -> row tid>>1, 32 cols at (tid&1)*32
    {
        int r = tid >> 1, c0 = (tid & 1) * 32;
        #pragma unroll
        for (int i = 0; i < 8; i++) {
            float4 v = *(const float4*)&Qg[(size_t)(q0 + r)*HD + c0 + i*4];
            uint4 u = {f2tf(v.x), f2tf(v.y), f2tf(v.z), f2tf(v.w)};
            *(uint4*)&Qs[r*AST + c0 + i*4] = u;
        }
    }

    // fragment lane addressing
    const int arow  = w*16 + (lane & 7) + ((lane >> 3) & 1) * 8;
    const unsigned qBase = QsB + (unsigned)((arow*AST + (lane >> 4)*4) * 4);
    const int brow  = lane & 7;
    const int bhalf = ((lane >> 3) & 1) * 4;
    const unsigned kBase = KsB + (unsigned)((brow*AST + bhalf) * 4);
    const unsigned vBase = VsB + (unsigned)((brow*AST + bhalf) * 4);

    float o[8][4] = {};
    float mrun0 = -1e30f, mrun1 = -1e30f;
    float lrun0 = 0.f, lrun1 = 0.f;

    const int t2 = (lane & 3) * 2;
    const int srcA = (lane & 28) | ((lane & 3) >> 1);
    const int sel  = lane & 1;

    for (int k0 = 0; k0 < SS; k0 += 64) {
        __syncthreads();
        // stage K (cvt) and V (cvt + transpose)
        {
            int r = tid >> 2, cq = tid & 3;
            #pragma unroll
            for (int i = 0; i < 4; i++) {
                int c = cq*16 + i*4;
                float4 kv = *(const float4*)&Kg[(size_t)(k0 + r)*HD + c];
                uint4 ku = {f2tf(kv.x), f2tf(kv.y), f2tf(kv.z), f2tf(kv.w)};
                *(uint4*)&Ks[r*AST + c] = ku;
                float4 vv = *(const float4*)&Vg[(size_t)(k0 + r)*HD + c];
                *(unsigned*)&VsT[(c+0)*AST + r] = f2tf(vv.x);
                *(unsigned*)&VsT[(c+1)*AST + r] = f2tf(vv.y);
                *(unsigned*)&VsT[(c+2)*AST + r] = f2tf(vv.z);
                *(unsigned*)&VsT[(c+3)*AST + r] = f2tf(vv.w);
            }
        }
        if (tid < 64) ms[tid] = -1e8f * (float)mg[k0 + tid];
        __syncthreads();

        // S = Q K^T
        float ss[8][4] = {};
        #pragma unroll
        for (int dc = 0; dc < 8; dc++) {
            unsigned aq[4];
            ldsm_x4(aq, qBase + (unsigned)(dc * 32));
            #pragma unroll
            for (int nt = 0; nt < 8; nt++) {
                unsigned bk[2];
                ldsm_x2(bk, kBase + (unsigned)((nt*8*AST + dc*8) * 4));
                mma_tf32(ss[nt], aq, bk);
            }
        }

        // scale + mask bias + row max (two rows per lane: g, g+8)
        float m0l = -1e30f, m1l = -1e30f;
        #pragma unroll
        for (int nt = 0; nt < 8; nt++) {
            float b0 = ms[nt*8 + t2], b1 = ms[nt*8 + t2 + 1];
            ss[nt][0] = ss[nt][0]*0.125f + b0;
            ss[nt][1] = ss[nt][1]*0.125f + b1;
            ss[nt][2] = ss[nt][2]*0.125f + b0;
            ss[nt][3] = ss[nt][3]*0.125f + b1;
            m0l = fmaxf(m0l, fmaxf(ss[nt][0], ss[nt][1]));
            m1l = fmaxf(m1l, fmaxf(ss[nt][2], ss[nt][3]));
        }
        m0l = fmaxf(m0l, __shfl_xor_sync(0xffffffffu, m0l, 1));
        m0l = fmaxf(m0l, __shfl_xor_sync(0xffffffffu, m0l, 2));
        m1l = fmaxf(m1l, __shfl_xor_sync(0xffffffffu, m1l, 1));
        m1l = fmaxf(m1l, __shfl_xor_sync(0xffffffffu, m1l, 2));

        float mnew0 = fmaxf(mrun0, m0l);
        float mnew1 = fmaxf(mrun1, m1l);
        float fac0 = __expf(mrun0 - mnew0);
        float fac1 = __expf(mrun1 - mnew1);
        mrun0 = mnew0; mrun1 = mnew1;

        float ps0 = 0.f, ps1 = 0.f;
        #pragma unroll
        for (int nt = 0; nt < 8; nt++) {
            ss[nt][0] = __expf(ss[nt][0] - mnew0);
            ss[nt][1] = __expf(ss[nt][1] - mnew0);
            ss[nt][2] = __expf(ss[nt][2] - mnew1);
            ss[nt][3] = __expf(ss[nt][3] - mnew1);
            ps0 += ss[nt][0] + ss[nt][1];
            ps1 += ss[nt][2] + ss[nt][3];
        }
        ps0 += __shfl_xor_sync(0xffffffffu, ps0, 1);
        ps0 += __shfl_xor_sync(0xffffffffu, ps0, 2);
        ps1 += __shfl_xor_sync(0xffffffffu, ps1, 1);
        ps1 += __shfl_xor_sync(0xffffffffu, ps1, 2);
        lrun0 = lrun0 * fac0 + ps0;
        lrun1 = lrun1 * fac1 + ps1;

        #pragma unroll
        for (int dt = 0; dt < 8; dt++) {
            o[dt][0] *= fac0; o[dt][1] *= fac0;
            o[dt][2] *= fac1; o[dt][3] *= fac1;
        }

        // O += P V  (convert P C-layout -> A-frag per 8-key chunk)
        #pragma unroll
        for (int kc = 0; kc < 8; kc++) {
            float x0 = __shfl_sync(0xffffffffu, ss[kc][0], srcA);
            float x1 = __shfl_sync(0xffffffffu, ss[kc][1], srcA);
            float y0 = __shfl_sync(0xffffffffu, ss[kc][0], srcA + 2);
            float y1 = __shfl_sync(0xffffffffu, ss[kc][1], srcA + 2);
            float z0 = __shfl_sync(0xffffffffu, ss[kc][2], srcA);
            float z1 = __shfl_sync(0xffffffffu, ss[kc][3], srcA);
            float w0 = __shfl_sync(0xffffffffu, ss[kc][2], srcA + 2);
            float w1 = __shfl_sync(0xffffffffu, ss[kc][3], srcA + 2);
            unsigned ap[4];
            ap[0] = f2tf(sel ? x1 : x0);
            ap[1] = f2tf(sel ? z1 : z0);
            ap[2] = f2tf(sel ? y1 : y0);
            ap[3] = f2tf(sel ? w1 : w0);
            #pragma unroll
            for (int dt = 0; dt < 8; dt++) {
                unsigned bv[2];
                ldsm_x2(bv, vBase + (unsigned)((dt*8*AST + kc*8) * 4));
                mma_tf32(o[dt], ap, bv);
            }
        }
    }

    // epilogue: write ctx [b, s, h*64 + d]
    float inv0 = 1.0f / lrun0, inv1 = 1.0f / lrun1;
    int r0 = q0 + w*16 + (lane >> 2);
    #pragma unroll
    for (int dt = 0; dt < 8; dt++) {
        int d = dt*8 + t2;
        float2 v0 = {o[dt][0]*inv0, o[dt][1]*inv0};
        float2 v1 = {o[dt][2]*inv1, o[dt][3]*inv1};
        *(float2*)&g_ctx[((size_t)b*SS + r0)*HH + h*HD + d]     = v0;
        *(float2*)&g_ctx[((size_t)b*SS + r0 + 8)*HH + h*HD + d] = v1;
    }
}

// ======================= launch ============================================
extern "C" void kernel_launch(void* const* d_in, const int* in_sizes, int n_in,
                              void* d_out, int out_size)
{
    const float* x      = (const float*)d_in[0];
    const int*   mask   = (const int*)  d_in[1];
    const float* qkv_w  = (const float*)d_in[2];
    const float* qkv_b  = (const float*)d_in[3];
    const float* out_w  = (const float*)d_in[4];
    const float* out_b  = (const float*)d_in[5];
    const float* gamma  = (const float*)d_in[6];
    const float* beta   = (const float*)d_in[7];
    float* out = (float*)d_out;

    const int attn_smem = 256*AST*4 + 64*4;   // 69888 B
    cudaFuncSetAttribute(attn_kernel,
                         cudaFuncAttributeMaxDynamicSharedMemorySize, attn_smem);

    // 1) LayerNorm
    ln_kernel<<<MM, 256>>>(x, gamma, beta);

    // 2) QKV projection: N=3072, M=8192
    gemm_qkv_kernel<<<dim3(3*HH/128, MM/128), 256>>>(qkv_w, qkv_b);

    // 3) attention: 16 q-tiles x 64 (b,h)
    attn_kernel<<<dim3(SS/128, BB*NH), 256, attn_smem>>>(mask);

    // 4) output projection + bias + residual
    gemm_out_kernel<<<dim3(HH/128, MM/128), 256>>>(out_w, out_b, x, out);
}

// round 5
// speedup vs baseline: 8.5905x; 1.9537x over previous
#include <cuda_runtime.h>
#include <cuda_bf16.h>
#include <math.h>

#define BB 4
#define SS 2048
#define HH 1024
#define NH 16
#define HD 64
#define MM (BB*SS)          // 8192 rows

// ---------------- scratch (device globals; no allocation allowed) ----------
__device__ __nv_bfloat16 g_y[BB*SS*HH];        // LN output        16 MB
__device__ __nv_bfloat16 g_q[BB*NH*SS*HD];     // Q [b,h,s,d]      16 MB
__device__ __nv_bfloat16 g_k[BB*NH*SS*HD];     // K [b,h,s,d]      16 MB
__device__ __nv_bfloat16 g_v[BB*NH*SS*HD];     // V [b,h,s,d]      16 MB
__device__ __nv_bfloat16 g_ctx[BB*SS*HH];      // attention ctx    16 MB

// ---------------- bf16 mma helpers -----------------------------------------
__device__ __forceinline__ unsigned pkbf(float lo, float hi) {
    __nv_bfloat162 h = __float22bfloat162_rn(make_float2(lo, hi));
    return *(unsigned*)&h;
}
// D(16x8,f32) += A(16x16,bf16,row) * B(16x8,bf16,col)
__device__ __forceinline__ void mma_bf16(float* d, const unsigned* a, const unsigned* b) {
    asm("mma.sync.aligned.m16n8k16.row.col.f32.bf16.bf16.f32 "
        "{%0,%1,%2,%3},{%4,%5,%6,%7},{%8,%9},{%0,%1,%2,%3};"
        : "+f"(d[0]), "+f"(d[1]), "+f"(d[2]), "+f"(d[3])
        : "r"(a[0]), "r"(a[1]), "r"(a[2]), "r"(a[3]), "r"(b[0]), "r"(b[1]));
}
__device__ __forceinline__ void ldsm_x4(unsigned* r, unsigned addr) {
    asm volatile("ldmatrix.sync.aligned.m8n8.x4.shared.b16 {%0,%1,%2,%3},[%4];"
        : "=r"(r[0]), "=r"(r[1]), "=r"(r[2]), "=r"(r[3]) : "r"(addr));
}
__device__ __forceinline__ void ldsm_x4t(unsigned* r, unsigned addr) {
    asm volatile("ldmatrix.sync.aligned.m8n8.x4.trans.shared.b16 {%0,%1,%2,%3},[%4];"
        : "=r"(r[0]), "=r"(r[1]), "=r"(r[2]), "=r"(r[3]) : "r"(addr));
}

// ======================= 1) LayerNorm (f32 in -> bf16 out) =================
__global__ void __launch_bounds__(256) ln_kernel(
    const float* __restrict__ x,
    const float* __restrict__ gamma,
    const float* __restrict__ beta)
{
    int row = blockIdx.x;
    int tid = threadIdx.x;
    const float4 xv = *(const float4*)&x[row*HH + tid*4];

    float s  = xv.x + xv.y + xv.z + xv.w;
    float s2 = xv.x*xv.x + xv.y*xv.y + xv.z*xv.z + xv.w*xv.w;
    #pragma unroll
    for (int o = 16; o > 0; o >>= 1) {
        s  += __shfl_down_sync(0xffffffffu, s,  o);
        s2 += __shfl_down_sync(0xffffffffu, s2, o);
    }
    __shared__ float ss[8], ss2[8];
    if ((tid & 31) == 0) { ss[tid >> 5] = s; ss2[tid >> 5] = s2; }
    __syncthreads();
    float ts = 0.f, ts2 = 0.f;
    #pragma unroll
    for (int w = 0; w < 8; w++) { ts += ss[w]; ts2 += ss2[w]; }

    float mu   = ts * (1.0f / HH);
    float var  = ts2 * (1.0f / HH) - mu * mu;
    float rstd = rsqrtf(var + 1e-5f);

    const float4 gv = *(const float4*)&gamma[tid*4];
    const float4 bv = *(const float4*)&beta[tid*4];
    uint2 o2;
    o2.x = pkbf((xv.x - mu)*rstd*gv.x + bv.x, (xv.y - mu)*rstd*gv.y + bv.y);
    o2.y = pkbf((xv.z - mu)*rstd*gv.z + bv.z, (xv.w - mu)*rstd*gv.w + bv.w);
    *(uint2*)&g_y[row*HH + tid*4] = o2;
}

// ======================= bf16 GEMM core (128x128, k-step 32) ===============
// C[m,n] = sum_k A[m,k] * W[n,k]; A bf16 (copy-staged), W f32 (cvt-staged).
// 8 warps as 2(m) x 4(n); warp tile 64x32 = 4 mt x 4 nt of m16n8k16.
#define GST 40   // smem row stride in halves; 80B = 5x16B (odd) -> conflict-free

// ---- QKV GEMM: epilogue scatters bf16 to g_q/g_k/g_v [b,h,s,d] ------------
__global__ void __launch_bounds__(256) gemm_qkv_kernel(
    const float* __restrict__ W,
    const float* __restrict__ bias)
{
    __shared__ __nv_bfloat16 As[128*GST];
    __shared__ __nv_bfloat16 Bs[128*GST];
    const int tid  = threadIdx.x;
    const int lane = tid & 31;
    const int w    = tid >> 5;
    const int warp_m = (w >> 2) * 64;
    const int warp_n = (w & 3) * 32;
    const int n0 = blockIdx.x * 128;
    const int m0 = blockIdx.y * 128;

    // staging: rows sr, sr+64; 8 halves at col sc
    const int sr = tid >> 2;
    const int sc = (tid & 3) * 8;
    const __nv_bfloat16* Ap = g_y + (size_t)(m0 + sr) * HH + sc;
    const float*         Bp = W   + (size_t)(n0 + sr) * HH + sc;

    unsigned AsB = (unsigned)__cvta_generic_to_shared(As);
    unsigned BsB = (unsigned)__cvta_generic_to_shared(Bs);

    const unsigned aBase = AsB + (unsigned)(((warp_m + (lane & 15))*GST + (lane >> 4)*8) * 2);
    const unsigned bBase = BsB + (unsigned)(((warp_n + (lane >> 4)*8 + (lane & 7))*GST + ((lane >> 3) & 1)*8) * 2);

    float acc[4][4][4] = {};
    uint4  ra[2];
    float4 rb[2][2];
    #pragma unroll
    for (int hf = 0; hf < 2; hf++) {
        ra[hf]    = *(const uint4*)(Ap + (size_t)hf*64*HH);
        rb[hf][0] = *(const float4*)(Bp + (size_t)hf*64*HH);
        rb[hf][1] = *(const float4*)(Bp + (size_t)hf*64*HH + 4);
    }

    for (int k0 = 0; k0 < HH; k0 += 32) {
        __syncthreads();
        #pragma unroll
        for (int hf = 0; hf < 2; hf++) {
            *(uint4*)&As[(sr + hf*64)*GST + sc] = ra[hf];
            uint4 ub;
            ub.x = pkbf(rb[hf][0].x, rb[hf][0].y);
            ub.y = pkbf(rb[hf][0].z, rb[hf][0].w);
            ub.z = pkbf(rb[hf][1].x, rb[hf][1].y);
            ub.w = pkbf(rb[hf][1].z, rb[hf][1].w);
            *(uint4*)&Bs[(sr + hf*64)*GST + sc] = ub;
        }
        __syncthreads();
        if (k0 + 32 < HH) {
            #pragma unroll
            for (int hf = 0; hf < 2; hf++) {
                ra[hf]    = *(const uint4*)(Ap + k0 + 32 + (size_t)hf*64*HH);
                rb[hf][0] = *(const float4*)(Bp + k0 + 32 + (size_t)hf*64*HH);
                rb[hf][1] = *(const float4*)(Bp + k0 + 32 + (size_t)hf*64*HH + 4);
            }
        }
        #pragma unroll
        for (int kc = 0; kc < 2; kc++) {
            unsigned af[4][4], bf[2][4];
            #pragma unroll
            for (int mt = 0; mt < 4; mt++)
                ldsm_x4(af[mt], aBase + (unsigned)((mt*16*GST + kc*16) * 2));
            #pragma unroll
            for (int np = 0; np < 2; np++)
                ldsm_x4(bf[np], bBase + (unsigned)((np*16*GST + kc*16) * 2));
            #pragma unroll
            for (int mt = 0; mt < 4; mt++)
                #pragma unroll
                for (int np = 0; np < 2; np++) {
                    mma_bf16(acc[mt][2*np],   af[mt], &bf[np][0]);
                    mma_bf16(acc[mt][2*np+1], af[mt], &bf[np][2]);
                }
        }
    }

    // epilogue: bf16 scatter to q/k/v [b,h,s,d]
    const int g = lane >> 2, t2 = (lane & 3) * 2;
    #pragma unroll
    for (int nt = 0; nt < 4; nt++) {
        int gn = n0 + warp_n + nt*8 + t2;
        int grp = gn >> 10, head = (gn >> 6) & 15, d = gn & 63;
        __nv_bfloat16* dst = (grp == 0) ? g_q : (grp == 1) ? g_k : g_v;
        float2 bi = *(const float2*)&bias[gn];
        #pragma unroll
        for (int mt = 0; mt < 4; mt++) {
            int m = m0 + warp_m + mt*16 + g;
            int b = m >> 11, s = m & 2047;
            __nv_bfloat16* p = &dst[((size_t)(b*NH + head)*SS + s)*HD + d];
            *(unsigned*)p          = pkbf(acc[mt][nt][0] + bi.x, acc[mt][nt][1] + bi.y);
            *(unsigned*)(p + 8*HD) = pkbf(acc[mt][nt][2] + bi.x, acc[mt][nt][3] + bi.y);
        }
    }
}

// ---- Output GEMM: + bias + residual (f32 out) -----------------------------
__global__ void __launch_bounds__(256) gemm_out_kernel(
    const float* __restrict__ W,
    const float* __restrict__ bias,
    const float* __restrict__ x,
    float* __restrict__ out)
{
    __shared__ __nv_bfloat16 As[128*GST];
    __shared__ __nv_bfloat16 Bs[128*GST];
    const int tid  = threadIdx.x;
    const int lane = tid & 31;
    const int w    = tid >> 5;
    const int warp_m = (w >> 2) * 64;
    const int warp_n = (w & 3) * 32;
    const int n0 = blockIdx.x * 128;
    const int m0 = blockIdx.y * 128;

    const int sr = tid >> 2;
    const int sc = (tid & 3) * 8;
    const __nv_bfloat16* Ap = g_ctx + (size_t)(m0 + sr) * HH + sc;
    const float*         Bp = W     + (size_t)(n0 + sr) * HH + sc;

    unsigned AsB = (unsigned)__cvta_generic_to_shared(As);
    unsigned BsB = (unsigned)__cvta_generic_to_shared(Bs);

    const unsigned aBase = AsB + (unsigned)(((warp_m + (lane & 15))*GST + (lane >> 4)*8) * 2);
    const unsigned bBase = BsB + (unsigned)(((warp_n + (lane >> 4)*8 + (lane & 7))*GST + ((lane >> 3) & 1)*8) * 2);

    float acc[4][4][4] = {};
    uint4  ra[2];
    float4 rb[2][2];
    #pragma unroll
    for (int hf = 0; hf < 2; hf++) {
        ra[hf]    = *(const uint4*)(Ap + (size_t)hf*64*HH);
        rb[hf][0] = *(const float4*)(Bp + (size_t)hf*64*HH);
        rb[hf][1] = *(const float4*)(Bp + (size_t)hf*64*HH + 4);
    }

    for (int k0 = 0; k0 < HH; k0 += 32) {
        __syncthreads();
        #pragma unroll
        for (int hf = 0; hf < 2; hf++) {
            *(uint4*)&As[(sr + hf*64)*GST + sc] = ra[hf];
            uint4 ub;
            ub.x = pkbf(rb[hf][0].x, rb[hf][0].y);
            ub.y = pkbf(rb[hf][0].z, rb[hf][0].w);
            ub.z = pkbf(rb[hf][1].x, rb[hf][1].y);
            ub.w = pkbf(rb[hf][1].z, rb[hf][1].w);
            *(uint4*)&Bs[(sr + hf*64)*GST + sc] = ub;
        }
        __syncthreads();
        if (k0 + 32 < HH) {
            #pragma unroll
            for (int hf = 0; hf < 2; hf++) {
                ra[hf]    = *(const uint4*)(Ap + k0 + 32 + (size_t)hf*64*HH);
                rb[hf][0] = *(const float4*)(Bp + k0 + 32 + (size_t)hf*64*HH);
                rb[hf][1] = *(const float4*)(Bp + k0 + 32 + (size_t)hf*64*HH + 4);
            }
        }
        #pragma unroll
        for (int kc = 0; kc < 2; kc++) {
            unsigned af[4][4], bf[2][4];
            #pragma unroll
            for (int mt = 0; mt < 4; mt++)
                ldsm_x4(af[mt], aBase + (unsigned)((mt*16*GST + kc*16) * 2));
            #pragma unroll
            for (int np = 0; np < 2; np++)
                ldsm_x4(bf[np], bBase + (unsigned)((np*16*GST + kc*16) * 2));
            #pragma unroll
            for (int mt = 0; mt < 4; mt++)
                #pragma unroll
                for (int np = 0; np < 2; np++) {
                    mma_bf16(acc[mt][2*np],   af[mt], &bf[np][0]);
                    mma_bf16(acc[mt][2*np+1], af[mt], &bf[np][2]);
                }
        }
    }

    const int g = lane >> 2, t2 = (lane & 3) * 2;
    #pragma unroll
    for (int nt = 0; nt < 4; nt++) {
        int gn = n0 + warp_n + nt*8 + t2;
        float2 bi = *(const float2*)&bias[gn];
        #pragma unroll
        for (int mt = 0; mt < 4; mt++) {
            int m = m0 + warp_m + mt*16 + g;
            const float2 x0 = *(const float2*)&x[(size_t)m*HH + gn];
            const float2 x1 = *(const float2*)&x[(size_t)(m+8)*HH + gn];
            float2 v0 = {acc[mt][nt][0] + bi.x + x0.x, acc[mt][nt][1] + bi.y + x0.y};
            float2 v1 = {acc[mt][nt][2] + bi.x + x1.x, acc[mt][nt][3] + bi.y + x1.y};
            *(float2*)&out[(size_t)m*HH + gn]     = v0;
            *(float2*)&out[(size_t)(m+8)*HH + gn] = v1;
        }
    }
}

// ======================= 3) Flash attention (bf16 mma) =====================
// 256 threads (8 warps); q-tile 128 (16 rows/warp), k-tile 64.
// Q fragments cached in regs; P->A fragment is a register bf16x2 pack
// (k16 A-fragment pair == C-fragment column pair); V read with ldmatrix.trans.
#define AST 72   // 144B = 9x16B (odd) -> conflict-free ldmatrix
__global__ void __launch_bounds__(256) attn_kernel(const int* __restrict__ mask)
{
    __shared__ __nv_bfloat16 Qs[128*AST];
    __shared__ __nv_bfloat16 Ks[64*AST];
    __shared__ __nv_bfloat16 Vs[64*AST];
    __shared__ float ms[64];

    const int tid  = threadIdx.x;
    const int lane = tid & 31;
    const int w    = tid >> 5;
    const int bh = blockIdx.y;
    const int q0 = blockIdx.x * 128;
    const int b  = bh >> 4, h = bh & 15;

    const __nv_bfloat16* Qg = g_q + (size_t)bh * SS * HD;
    const __nv_bfloat16* Kg = g_k + (size_t)bh * SS * HD;
    const __nv_bfloat16* Vg = g_v + (size_t)bh * SS * HD;
    const int*           mg = mask + b * SS;

    const unsigned QsB = (unsigned)__cvta_generic_to_shared(Qs);
    const unsigned KsB = (unsigned)__cvta_generic_to_shared(Ks);
    const unsigned VsB = (unsigned)__cvta_generic_to_shared(Vs);

    // stage Q (bf16 copy): row tid>>1, 32 halves at (tid&1)*32
    {
        int r = tid >> 1, c0 = (tid & 1) * 32;
        #pragma unroll
        for (int i = 0; i < 4; i++)
            *(uint4*)&Qs[r*AST + c0 + i*8] =
                *(const uint4*)&Qg[(size_t)(q0 + r)*HD + c0 + i*8];
    }
    __syncthreads();

    // cache Q fragments (4 d-chunks)
    const unsigned qBase = QsB + (unsigned)(((w*16 + (lane & 15))*AST + (lane >> 4)*8) * 2);
    unsigned qf[4][4];
    #pragma unroll
    for (int dc = 0; dc < 4; dc++)
        ldsm_x4(qf[dc], qBase + (unsigned)(dc*16*2));

    const unsigned kBase = KsB + (unsigned)((((lane >> 4)*8 + (lane & 7))*AST + ((lane >> 3) & 1)*8) * 2);
    const unsigned vBase = VsB + (unsigned)(((((lane >> 3) & 1)*8 + (lane & 7))*AST + (lane >> 4)*8) * 2);

    float o[8][4] = {};
    float mrun0 = -1e30f, mrun1 = -1e30f;
    float lrun0 = 0.f, lrun1 = 0.f;
    const int t2 = (lane & 3) * 2;

    for (int k0 = 0; k0 < SS; k0 += 64) {
        __syncthreads();
        // stage K, V (bf16 copy): row tid>>2, 16 halves at (tid&3)*16
        {
            int r = tid >> 2, c0 = (tid & 3) * 16;
            *(uint4*)&Ks[r*AST + c0]     = *(const uint4*)&Kg[(size_t)(k0 + r)*HD + c0];
            *(uint4*)&Ks[r*AST + c0 + 8] = *(const uint4*)&Kg[(size_t)(k0 + r)*HD + c0 + 8];
            *(uint4*)&Vs[r*AST + c0]     = *(const uint4*)&Vg[(size_t)(k0 + r)*HD + c0];
            *(uint4*)&Vs[r*AST + c0 + 8] = *(const uint4*)&Vg[(size_t)(k0 + r)*HD + c0 + 8];
        }
        if (tid < 64) ms[tid] = -1e8f * (float)mg[k0 + tid];
        __syncthreads();

        // S = Q K^T
        float ss[8][4] = {};
        #pragma unroll
        for (int dc = 0; dc < 4; dc++) {
            #pragma unroll
            for (int np = 0; np < 4; np++) {
                unsigned bk[4];
                ldsm_x4(bk, kBase + (unsigned)((np*16*AST + dc*16) * 2));
                mma_bf16(ss[2*np],   qf[dc], &bk[0]);
                mma_bf16(ss[2*np+1], qf[dc], &bk[2]);
            }
        }

        // scale + mask bias + row max (rows g, g+8)
        float m0l = -1e30f, m1l = -1e30f;
        #pragma unroll
        for (int nt = 0; nt < 8; nt++) {
            float b0 = ms[nt*8 + t2], b1 = ms[nt*8 + t2 + 1];
            ss[nt][0] = ss[nt][0]*0.125f + b0;
            ss[nt][1] = ss[nt][1]*0.125f + b1;
            ss[nt][2] = ss[nt][2]*0.125f + b0;
            ss[nt][3] = ss[nt][3]*0.125f + b1;
            m0l = fmaxf(m0l, fmaxf(ss[nt][0], ss[nt][1]));
            m1l = fmaxf(m1l, fmaxf(ss[nt][2], ss[nt][3]));
        }
        m0l = fmaxf(m0l, __shfl_xor_sync(0xffffffffu, m0l, 1));
        m0l = fmaxf(m0l, __shfl_xor_sync(0xffffffffu, m0l, 2));
        m1l = fmaxf(m1l, __shfl_xor_sync(0xffffffffu, m1l, 1));
        m1l = fmaxf(m1l, __shfl_xor_sync(0xffffffffu, m1l, 2));

        float mnew0 = fmaxf(mrun0, m0l);
        float mnew1 = fmaxf(mrun1, m1l);
        float fac0 = __expf(mrun0 - mnew0);
        float fac1 = __expf(mrun1 - mnew1);
        mrun0 = mnew0; mrun1 = mnew1;

        float ps0 = 0.f, ps1 = 0.f;
        #pragma unroll
        for (int nt = 0; nt < 8; nt++) {
            ss[nt][0] = __expf(ss[nt][0] - mnew0);
            ss[nt][1] = __expf(ss[nt][1] - mnew0);
            ss[nt][2] = __expf(ss[nt][2] - mnew1);
            ss[nt][3] = __expf(ss[nt][3] - mnew1);
            ps0 += ss[nt][0] + ss[nt][1];
            ps1 += ss[nt][2] + ss[nt][3];
        }
        ps0 += __shfl_xor_sync(0xffffffffu, ps0, 1);
        ps0 += __shfl_xor_sync(0xffffffffu, ps0, 2);
        ps1 += __shfl_xor_sync(0xffffffffu, ps1, 1);
        ps1 += __shfl_xor_sync(0xffffffffu, ps1, 2);
        lrun0 = lrun0 * fac0 + ps0;
        lrun1 = lrun1 * fac1 + ps1;

        #pragma unroll
        for (int dt = 0; dt < 8; dt++) {
            o[dt][0] *= fac0; o[dt][1] *= fac0;
            o[dt][2] *= fac1; o[dt][3] *= fac1;
        }

        // O += P V  (A-frag = packed score pairs; B via ldmatrix.trans)
        #pragma unroll
        for (int kc = 0; kc < 4; kc++) {
            unsigned ap[4];
            ap[0] = pkbf(ss[2*kc][0],   ss[2*kc][1]);
            ap[1] = pkbf(ss[2*kc][2],   ss[2*kc][3]);
            ap[2] = pkbf(ss[2*kc+1][0], ss[2*kc+1][1]);
            ap[3] = pkbf(ss[2*kc+1][2], ss[2*kc+1][3]);
            #pragma unroll
            for (int p = 0; p < 4; p++) {
                unsigned bv[4];
                ldsm_x4t(bv, vBase + (unsigned)((kc*16*AST + p*16) * 2));
                mma_bf16(o[2*p],   ap, &bv[0]);
                mma_bf16(o[2*p+1], ap, &bv[2]);
            }
        }
    }

    // epilogue: bf16 ctx [b, s, h*64 + d]
    float inv0 = 1.0f / lrun0, inv1 = 1.0f / lrun1;
    int r0 = q0 + w*16 + (lane >> 2);
    #pragma unroll
    for (int dt = 0; dt < 8; dt++) {
        int d = dt*8 + t2;
        *(unsigned*)&g_ctx[((size_t)b*SS + r0)*HH + h*HD + d] =
            pkbf(o[dt][0]*inv0, o[dt][1]*inv0);
        *(unsigned*)&g_ctx[((size_t)b*SS + r0 + 8)*HH + h*HD + d] =
            pkbf(o[dt][2]*inv1, o[dt][3]*inv1);
    }
}

// ======================= launch ============================================
extern "C" void kernel_launch(void* const* d_in, const int* in_sizes, int n_in,
                              void* d_out, int out_size)
{
    const float* x      = (const float*)d_in[0];
    const int*   mask   = (const int*)  d_in[1];
    const float* qkv_w  = (const float*)d_in[2];
    const float* qkv_b  = (const float*)d_in[3];
    const float* out_w  = (const float*)d_in[4];
    const float* out_b  = (const float*)d_in[5];
    const float* gamma  = (const float*)d_in[6];
    const float* beta   = (const float*)d_in[7];
    float* out = (float*)d_out;

    // 1) LayerNorm (f32 -> bf16)
    ln_kernel<<<MM, 256>>>(x, gamma, beta);

    // 2) QKV projection: N=3072, M=8192
    gemm_qkv_kernel<<<dim3(3*HH/128, MM/128), 256>>>(qkv_w, qkv_b);

    // 3) attention: 16 q-tiles x 64 (b,h)
    attn_kernel<<<dim3(SS/128, BB*NH), 256>>>(mask);

    // 4) output projection + bias + residual
    gemm_out_kernel<<<dim3(HH/128, MM/128), 256>>>(out_w, out_b, x, out);
}